// round 2
// baseline (speedup 1.0000x reference)
#include <cuda_runtime.h>

// S4/DPLR kernel materialization, H=256 heads, N2=64 complex state, RANK=1, CH=1.
// One warp per head; each lane holds state elements n=lane and n=lane+32.
// dA x = e.*x - (u^T x) .* q   (diagonal + rank-1 Woodbury form),
// so each step needs 3 fp32 warp reductions (Re/Im of u^T x, Re of C^T x),
// done with shfl.xor butterflies (redux.f32 does not exist on sm_103a).

#define N2 64

__global__ __launch_bounds__(64, 1) void ssm_dplr_kernel(
    const float* __restrict__ Ar, const float* __restrict__ Ai,
    const float* __restrict__ Br, const float* __restrict__ Bi,
    const float* __restrict__ Pr, const float* __restrict__ Pi,
    const float* __restrict__ Cr, const float* __restrict__ Ci,
    const float* __restrict__ logdt,
    float* __restrict__ out, int H, int L)
{
    const int h = blockIdx.x * (blockDim.x >> 5) + (threadIdx.x >> 5);
    if (h >= H) return;
    const int lane = threadIdx.x & 31;
    const int n0 = h * N2 + lane;
    const int n1 = n0 + 32;

    const float dt  = expf(logdt[h]);
    const float del = 0.5f * dt;

    // Lambda = -A_real - i A_imag
    const float l0r = -Ar[n0], l0i = -Ai[n0];
    const float l1r = -Ar[n1], l1i = -Ai[n1];

    // a = 1 + del*Lambda ; m = 1 - del*Lambda ; d = 1/m
    const float a0r = 1.f + del * l0r, a0i = del * l0i;
    const float a1r = 1.f + del * l1r, a1i = del * l1i;
    const float m0r = 1.f - del * l0r, m0i = -del * l0i;
    const float m1r = 1.f - del * l1r, m1i = -del * l1i;
    const float id0 = 1.f / (m0r * m0r + m0i * m0i);
    const float id1 = 1.f / (m1r * m1r + m1i * m1i);
    const float d0r = m0r * id0, d0i = -m0i * id0;
    const float d1r = m1r * id1, d1i = -m1i * id1;

    const float p0r = Pr[n0], p0i = Pi[n0];
    const float p1r = Pr[n1], p1i = Pi[n1];

    // e = d*a ; q = d*p ; g = conj(p)*e
    const float e0r = d0r * a0r - d0i * a0i, e0i = d0r * a0i + d0i * a0r;
    const float e1r = d1r * a1r - d1i * a1i, e1i = d1r * a1i + d1i * a1r;
    const float q0r = d0r * p0r - d0i * p0i, q0i = d0r * p0i + d0i * p0r;
    const float q1r = d1r * p1r - d1i * p1i, q1i = d1r * p1i + d1i * p1r;
    const float g0r = p0r * e0r + p0i * e0i, g0i = p0r * e0i - p0i * e0r;
    const float g1r = p1r * e1r + p1i * e1i, g1i = p1r * e1i - p1i * e1r;

    const float c0r = Cr[n0], c0i = Ci[n0];
    const float c1r = Cr[n1], c1i = Ci[n1];

    // kappa = sum_n d_n * |p_n|^2   (complex), via shuffle butterfly
    const float pp0 = p0r * p0r + p0i * p0i;
    const float pp1 = p1r * p1r + p1i * p1i;
    float kr = d0r * pp0 + d1r * pp1;
    float ki = d0i * pp0 + d1i * pp1;
    #pragma unroll
    for (int o = 16; o; o >>= 1) {
        kr += __shfl_xor_sync(0xffffffffu, kr, o);
        ki += __shfl_xor_sync(0xffffffffu, ki, o);
    }

    // gamma = del / (1 + del*kappa) ; dk = del*kappa
    const float wr = 1.f + del * kr, wi = del * ki;
    const float iw = 1.f / (wr * wr + wi * wi);
    const float gar = del * wr * iw, gai = -del * wi * iw;
    const float dkr = del * kr, dki = del * ki;

    // alpha = del - gamma*del*kappa   (complex); sc = alpha*t + gamma*s0
    const float alr = del - (gar * dkr - gai * dki);
    const float ali = -(gar * dki + gai * dkr);

    // u_n = alpha * conj(p_n) + gamma * g_n  -> sc = sum u_n x_n
    const float u0r = alr * p0r + ali * p0i + gar * g0r - gai * g0i;
    const float u0i = -alr * p0i + ali * p0r + gar * g0i + gai * g0r;
    const float u1r = alr * p1r + ali * p1i + gar * g1r - gai * g1i;
    const float u1i = -alr * p1i + ali * p1r + gar * g1i + gai * g1r;

    // dB = (I - del*A)^{-1} (dt*B): mm = d.*(dt*B); tau = p^H mm; x = mm - (gamma*tau).*q
    const float z0r = dt * Br[n0], z0i = dt * Bi[n0];
    const float z1r = dt * Br[n1], z1i = dt * Bi[n1];
    const float mm0r = d0r * z0r - d0i * z0i, mm0i = d0r * z0i + d0i * z0r;
    const float mm1r = d1r * z1r - d1i * z1i, mm1i = d1r * z1i + d1i * z1r;
    float taur = p0r * mm0r + p0i * mm0i + p1r * mm1r + p1i * mm1i;
    float taui = p0r * mm0i - p0i * mm0r + p1r * mm1i - p1i * mm1r;
    #pragma unroll
    for (int o = 16; o; o >>= 1) {
        taur += __shfl_xor_sync(0xffffffffu, taur, o);
        taui += __shfl_xor_sync(0xffffffffu, taui, o);
    }
    const float gtr = gar * taur - gai * taui;
    const float gti = gar * taui + gai * taur;

    float x0r = mm0r - (gtr * q0r - gti * q0i);
    float x0i = mm0i - (gtr * q0i + gti * q0r);
    float x1r = mm1r - (gtr * q1r - gti * q1i);
    float x1i = mm1i - (gtr * q1i + gti * q1r);

    float* __restrict__ o_ptr = out + (long)h * L;

    #pragma unroll 2
    for (int l = 0; l < L; ++l) {
        // sc = sum u_n x_n ; kk = Re(sum C_n x_n)
        float sr = u0r * x0r - u0i * x0i + u1r * x1r - u1i * x1i;
        float si = u0r * x0i + u0i * x0r + u1r * x1i + u1i * x1r;
        float kk = c0r * x0r - c0i * x0i + c1r * x1r - c1i * x1i;

        #pragma unroll
        for (int o = 16; o; o >>= 1) {
            sr += __shfl_xor_sync(0xffffffffu, sr, o);
            si += __shfl_xor_sync(0xffffffffu, si, o);
            kk += __shfl_xor_sync(0xffffffffu, kk, o);
        }

        if (lane == 0) o_ptr[l] = 2.f * kk;

        // x <- e .* x - sc .* q
        const float nx0r = e0r * x0r - e0i * x0i - (sr * q0r - si * q0i);
        const float nx0i = e0r * x0i + e0i * x0r - (sr * q0i + si * q0r);
        const float nx1r = e1r * x1r - e1i * x1i - (sr * q1r - si * q1i);
        const float nx1i = e1r * x1i + e1i * x1r - (sr * q1i + si * q1r);
        x0r = nx0r; x0i = nx0i; x1r = nx1r; x1i = nx1i;
    }
}

extern "C" void kernel_launch(void* const* d_in, const int* in_sizes, int n_in,
                              void* d_out, int out_size) {
    const float* Ar = (const float*)d_in[0];
    const float* Ai = (const float*)d_in[1];
    const float* Br = (const float*)d_in[2];
    const float* Bi = (const float*)d_in[3];
    const float* Pr = (const float*)d_in[4];
    const float* Pi = (const float*)d_in[5];
    const float* Cr = (const float*)d_in[6];
    const float* Ci = (const float*)d_in[7];
    const float* ld = (const float*)d_in[8];
    float* out = (float*)d_out;

    const int H = in_sizes[8];          // 256
    const int L = out_size / H;         // CH = 1 -> 2048

    const int warps_per_block = 2;
    const int blocks = (H + warps_per_block - 1) / warps_per_block;
    ssm_dplr_kernel<<<blocks, warps_per_block * 32>>>(
        Ar, Ai, Br, Bi, Pr, Pi, Cr, Ci, ld, out, H, L);
}

// round 3
// speedup vs baseline: 1.7733x; 1.7733x over previous
#include <cuda_runtime.h>

// S4/DPLR kernel materialization, H=256, N2=64, RANK=1, CH=1, L=2048.
// dA = E - q u^T (diagonal + rank-1). J-blocked recurrence: per block of J
// steps, compute 3J independent warp reductions (mu_m re/im, kappa_m re) on
// the block base state, then recombine with precomputed scalars nu/eta and
// do one block-end diagonal+rank-J state update.

#define N2 64
#define J 4

__device__ __forceinline__ float wsum(float v) {
    #pragma unroll
    for (int o = 16; o; o >>= 1) v += __shfl_xor_sync(0xffffffffu, v, o);
    return v;
}

__global__ __launch_bounds__(64, 1) void ssm_dplr_kernel(
    const float* __restrict__ Ar, const float* __restrict__ Ai,
    const float* __restrict__ Br, const float* __restrict__ Bi,
    const float* __restrict__ Pr, const float* __restrict__ Pi,
    const float* __restrict__ Cr, const float* __restrict__ Ci,
    const float* __restrict__ logdt,
    float* __restrict__ out, int H, int L)
{
    const int h = blockIdx.x * (blockDim.x >> 5) + (threadIdx.x >> 5);
    if (h >= H) return;
    const int lane = threadIdx.x & 31;
    const int base = h * N2 + lane;

    const float dt  = expf(logdt[h]);
    const float del = 0.5f * dt;

    // per-slot complex params (slot s holds state index lane + 32*s)
    float er[2], ei[2], qr[2], qi[2], ur_[2], ui_[2], c2r[2], c2i[2];
    float pr[2], pi[2], d_r[2], d_i[2], g_r[2], g_i[2];

    float kpr = 0.f, kpi = 0.f;   // kappa = sum d |p|^2
    #pragma unroll
    for (int s = 0; s < 2; ++s) {
        const int n = base + 32 * s;
        const float lr = -Ar[n], li = -Ai[n];
        const float ar = 1.f + del * lr, ai = del * li;
        const float mr = 1.f - del * lr, mi = -del * li;
        const float idm = 1.f / (mr * mr + mi * mi);
        d_r[s] = mr * idm; d_i[s] = -mi * idm;
        pr[s] = Pr[n]; pi[s] = Pi[n];
        // e = d*a ; q = d*p ; g = conj(p)*e
        er[s] = d_r[s] * ar - d_i[s] * ai;  ei[s] = d_r[s] * ai + d_i[s] * ar;
        qr[s] = d_r[s] * pr[s] - d_i[s] * pi[s];
        qi[s] = d_r[s] * pi[s] + d_i[s] * pr[s];
        g_r[s] = pr[s] * er[s] + pi[s] * ei[s];
        g_i[s] = pr[s] * ei[s] - pi[s] * er[s];
        c2r[s] = 2.f * Cr[n]; c2i[s] = 2.f * Ci[n];
        const float pp = pr[s] * pr[s] + pi[s] * pi[s];
        kpr += d_r[s] * pp; kpi += d_i[s] * pp;
    }
    kpr = wsum(kpr); kpi = wsum(kpi);

    // gamma = del/(1+del*kappa); alpha = del - gamma*del*kappa
    const float wr = 1.f + del * kpr, wi = del * kpi;
    const float iw = 1.f / (wr * wr + wi * wi);
    const float gar = del * wr * iw, gai = -del * wi * iw;
    const float dkr = del * kpr, dki = del * kpi;
    const float alr = del - (gar * dkr - gai * dki);
    const float ali = -(gar * dki + gai * dkr);

    // u = alpha*conj(p) + gamma*g
    #pragma unroll
    for (int s = 0; s < 2; ++s) {
        ur_[s] = alr * pr[s] + ali * pi[s] + gar * g_r[s] - gai * g_i[s];
        ui_[s] = -alr * pi[s] + ali * pr[s] + gar * g_i[s] + gai * g_r[s];
    }

    // Precompute per-m constants: uE_m = u.*e^m, cE_m = c2.*e^m, qE_m = e^m.*q
    float uEr[J][2], uEi[J][2], cEr[J][2], cEi[J][2], qEr[J][2], qEi[J][2];
    float eJr[2], eJi[2];
    {
        float emr[2] = {1.f, 1.f}, emi[2] = {0.f, 0.f};
        #pragma unroll
        for (int m = 0; m < J; ++m) {
            #pragma unroll
            for (int s = 0; s < 2; ++s) {
                uEr[m][s] = ur_[s] * emr[s] - ui_[s] * emi[s];
                uEi[m][s] = ur_[s] * emi[s] + ui_[s] * emr[s];
                cEr[m][s] = c2r[s] * emr[s] - c2i[s] * emi[s];
                cEi[m][s] = c2r[s] * emi[s] + c2i[s] * emr[s];
                qEr[m][s] = qr[s] * emr[s] - qi[s] * emi[s];
                qEi[m][s] = qr[s] * emi[s] + qi[s] * emr[s];
                const float tr2 = emr[s] * er[s] - emi[s] * ei[s];
                emi[s] = emr[s] * ei[s] + emi[s] * er[s];
                emr[s] = tr2;
            }
        }
        eJr[0] = emr[0]; eJi[0] = emi[0]; eJr[1] = emr[1]; eJi[1] = emi[1];
    }

    // Scalars nu_m = u^T E^m q, eta_m = c2^T E^m q (complex), via reductions
    float nur[J], nui[J], etr[J], eti[J];
    #pragma unroll
    for (int m = 0; m < J; ++m) {
        float a = 0.f, b = 0.f, c = 0.f, d = 0.f;
        #pragma unroll
        for (int s = 0; s < 2; ++s) {
            a += ur_[s] * qEr[m][s] - ui_[s] * qEi[m][s];
            b += ur_[s] * qEi[m][s] + ui_[s] * qEr[m][s];
            c += c2r[s] * qEr[m][s] - c2i[s] * qEi[m][s];
            d += c2r[s] * qEi[m][s] + c2i[s] * qEr[m][s];
        }
        nur[m] = wsum(a); nui[m] = wsum(b);
        etr[m] = wsum(c); eti[m] = wsum(d);
    }

    // Initial state x = dB = (I - del*A)^{-1} (dt*B) via Woodbury
    float xr[2], xi[2];
    {
        float mmr[2], mmi[2];
        float taur = 0.f, taui = 0.f;
        #pragma unroll
        for (int s = 0; s < 2; ++s) {
            const int n = base + 32 * s;
            const float zr = dt * Br[n], zi = dt * Bi[n];
            mmr[s] = d_r[s] * zr - d_i[s] * zi;
            mmi[s] = d_r[s] * zi + d_i[s] * zr;
            taur += pr[s] * mmr[s] + pi[s] * mmi[s];
            taui += pr[s] * mmi[s] - pi[s] * mmr[s];
        }
        taur = wsum(taur); taui = wsum(taui);
        const float gtr = gar * taur - gai * taui;
        const float gti = gar * taui + gai * taur;
        #pragma unroll
        for (int s = 0; s < 2; ++s) {
            xr[s] = mmr[s] - (gtr * qr[s] - gti * qi[s]);
            xi[s] = mmi[s] - (gtr * qi[s] + gti * qr[s]);
        }
    }

    float* __restrict__ o_ptr = out + (long)h * L;
    const int Lb = L & ~(J - 1);

    #pragma unroll 1
    for (int l = 0; l < Lb; l += J) {
        // moments on block base state
        float mur[J], mui[J], kap[J];
        #pragma unroll
        for (int m = 0; m < J; ++m) {
            mur[m] = uEr[m][0] * xr[0] - uEi[m][0] * xi[0]
                   + uEr[m][1] * xr[1] - uEi[m][1] * xi[1];
            mui[m] = uEr[m][0] * xi[0] + uEi[m][0] * xr[0]
                   + uEr[m][1] * xi[1] + uEi[m][1] * xr[1];
            kap[m] = cEr[m][0] * xr[0] - cEi[m][0] * xi[0]
                   + cEr[m][1] * xr[1] - cEi[m][1] * xi[1];
        }
        // 3J independent butterfly trees (interleaved)
        #pragma unroll
        for (int o = 16; o; o >>= 1) {
            #pragma unroll
            for (int m = 0; m < J; ++m) {
                mur[m] += __shfl_xor_sync(0xffffffffu, mur[m], o);
                mui[m] += __shfl_xor_sync(0xffffffffu, mui[m], o);
                kap[m] += __shfl_xor_sync(0xffffffffu, kap[m], o);
            }
        }

        // scalar recombination: t_m, k_m
        float tr[J], ti[J], kk[J];
        #pragma unroll
        for (int m = 0; m < J; ++m) {
            float ar = mur[m], ai = mui[m], kv = kap[m];
            #pragma unroll
            for (int j = 0; j < m; ++j) {
                const int i = m - 1 - j;
                ar -= nur[i] * tr[j] - nui[i] * ti[j];
                ai -= nur[i] * ti[j] + nui[i] * tr[j];
                kv -= etr[i] * tr[j] - eti[i] * ti[j];
            }
            tr[m] = ar; ti[m] = ai; kk[m] = kv;
        }

        if (lane == 0) {
            float4 v = make_float4(kk[0], kk[1], kk[2], kk[3]);
            *reinterpret_cast<float4*>(o_ptr + l) = v;
        }

        // block-end state update: x <- e^J.*x - sum_m t_m .* (E^{J-1-m} q)
        #pragma unroll
        for (int s = 0; s < 2; ++s) {
            float nxr = eJr[s] * xr[s] - eJi[s] * xi[s];
            float nxi = eJr[s] * xi[s] + eJi[s] * xr[s];
            #pragma unroll
            for (int m = 0; m < J; ++m) {
                const int i = J - 1 - m;
                nxr -= qEr[i][s] * tr[m] - qEi[i][s] * ti[m];
                nxi -= qEr[i][s] * ti[m] + qEi[i][s] * tr[m];
            }
            xr[s] = nxr; xi[s] = nxi;
        }
    }

    // remainder (L not divisible by J) — scalar steps
    for (int l = Lb; l < L; ++l) {
        float sr = uEr[0][0] * xr[0] - uEi[0][0] * xi[0]
                 + uEr[0][1] * xr[1] - uEi[0][1] * xi[1];
        float si = uEr[0][0] * xi[0] + uEi[0][0] * xr[0]
                 + uEr[0][1] * xi[1] + uEi[0][1] * xr[1];
        float kv = cEr[0][0] * xr[0] - cEi[0][0] * xi[0]
                 + cEr[0][1] * xr[1] - cEi[0][1] * xi[1];
        sr = wsum(sr); si = wsum(si); kv = wsum(kv);
        if (lane == 0) o_ptr[l] = kv;
        #pragma unroll
        for (int s = 0; s < 2; ++s) {
            const float nxr = er[s] * xr[s] - ei[s] * xi[s] - (sr * qr[s] - si * qi[s]);
            const float nxi = er[s] * xi[s] + ei[s] * xr[s] - (sr * qi[s] + si * qr[s]);
            xr[s] = nxr; xi[s] = nxi;
        }
    }
}

extern "C" void kernel_launch(void* const* d_in, const int* in_sizes, int n_in,
                              void* d_out, int out_size) {
    const float* Ar = (const float*)d_in[0];
    const float* Ai = (const float*)d_in[1];
    const float* Br = (const float*)d_in[2];
    const float* Bi = (const float*)d_in[3];
    const float* Pr = (const float*)d_in[4];
    const float* Pi = (const float*)d_in[5];
    const float* Cr = (const float*)d_in[6];
    const float* Ci = (const float*)d_in[7];
    const float* ld = (const float*)d_in[8];
    float* out = (float*)d_out;

    const int H = in_sizes[8];          // 256
    const int L = out_size / H;         // CH = 1 -> 2048

    const int warps_per_block = 2;
    const int blocks = (H + warps_per_block - 1) / warps_per_block;
    ssm_dplr_kernel<<<blocks, warps_per_block * 32>>>(
        Ar, Ai, Br, Bi, Pr, Pi, Cr, Ci, ld, out, H, L);
}

// round 4
// speedup vs baseline: 1.7834x; 1.0057x over previous
#include <cuda_runtime.h>

// S4/DPLR kernel materialization, H=256, N2=64, RANK=1, CH=1, L=2048.
// J-blocked rank-1 Woodbury recurrence, one warp per head (lane holds states
// n=lane, n=lane+32). This round: pack the two per-lane slots into f32x2
// (fma.rn.f32x2 / add.rn.f32x2) to halve FFMA-pipe issue slots, since a lone
// warp per SMSP is capped at 0.5 scalar FFMA/cyc (rt_SMSP=2).

#define N2 64
#define J 4

__device__ __forceinline__ float wsum(float v) {
    #pragma unroll
    for (int o = 16; o; o >>= 1) v += __shfl_xor_sync(0xffffffffu, v, o);
    return v;
}

__device__ __forceinline__ float2 f2(float x, float y) { return make_float2(x, y); }

__device__ __forceinline__ float2 ffma2(float2 a, float2 b, float2 c) {
    float2 d;
    asm("{\n\t.reg .b64 x,y,z,w;\n\t"
        "mov.b64 x,{%2,%3};\n\tmov.b64 y,{%4,%5};\n\tmov.b64 z,{%6,%7};\n\t"
        "fma.rn.f32x2 w,x,y,z;\n\t"
        "mov.b64 {%0,%1},w;\n\t}"
        : "=f"(d.x), "=f"(d.y)
        : "f"(a.x), "f"(a.y), "f"(b.x), "f"(b.y), "f"(c.x), "f"(c.y));
    return d;
}

__device__ __forceinline__ float2 fmul2(float2 a, float2 b) {
    float2 d;
    asm("{\n\t.reg .b64 x,y,w;\n\t"
        "mov.b64 x,{%2,%3};\n\tmov.b64 y,{%4,%5};\n\t"
        "mul.rn.f32x2 w,x,y;\n\t"
        "mov.b64 {%0,%1},w;\n\t}"
        : "=f"(d.x), "=f"(d.y)
        : "f"(a.x), "f"(a.y), "f"(b.x), "f"(b.y));
    return d;
}

__device__ __forceinline__ float2 fadd2(float2 a, float2 b) {
    float2 d;
    asm("{\n\t.reg .b64 x,y,w;\n\t"
        "mov.b64 x,{%2,%3};\n\tmov.b64 y,{%4,%5};\n\t"
        "add.rn.f32x2 w,x,y;\n\t"
        "mov.b64 {%0,%1},w;\n\t}"
        : "=f"(d.x), "=f"(d.y)
        : "f"(a.x), "f"(a.y), "f"(b.x), "f"(b.y));
    return d;
}

__global__ __launch_bounds__(64, 1) void ssm_dplr_kernel(
    const float* __restrict__ Ar, const float* __restrict__ Ai,
    const float* __restrict__ Br, const float* __restrict__ Bi,
    const float* __restrict__ Pr, const float* __restrict__ Pi,
    const float* __restrict__ Cr, const float* __restrict__ Ci,
    const float* __restrict__ logdt,
    float* __restrict__ out, int H, int L)
{
    const int h = blockIdx.x * (blockDim.x >> 5) + (threadIdx.x >> 5);
    if (h >= H) return;
    const int lane = threadIdx.x & 31;
    const int base = h * N2 + lane;

    const float dt  = expf(logdt[h]);
    const float del = 0.5f * dt;

    // ---- scalar setup (once; negligible) ----
    float er[2], ei[2], qr[2], qi[2], ur_[2], ui_[2], c2r[2], c2i[2];
    float pr[2], pi[2], d_r[2], d_i[2], g_r[2], g_i[2];

    float kpr = 0.f, kpi = 0.f;
    #pragma unroll
    for (int s = 0; s < 2; ++s) {
        const int n = base + 32 * s;
        const float lr = -Ar[n], li = -Ai[n];
        const float ar = 1.f + del * lr, ai = del * li;
        const float mr = 1.f - del * lr, mi = -del * li;
        const float idm = 1.f / (mr * mr + mi * mi);
        d_r[s] = mr * idm; d_i[s] = -mi * idm;
        pr[s] = Pr[n]; pi[s] = Pi[n];
        er[s] = d_r[s] * ar - d_i[s] * ai;  ei[s] = d_r[s] * ai + d_i[s] * ar;
        qr[s] = d_r[s] * pr[s] - d_i[s] * pi[s];
        qi[s] = d_r[s] * pi[s] + d_i[s] * pr[s];
        g_r[s] = pr[s] * er[s] + pi[s] * ei[s];
        g_i[s] = pr[s] * ei[s] - pi[s] * er[s];
        c2r[s] = 2.f * Cr[n]; c2i[s] = 2.f * Ci[n];
        const float pp = pr[s] * pr[s] + pi[s] * pi[s];
        kpr += d_r[s] * pp; kpi += d_i[s] * pp;
    }
    kpr = wsum(kpr); kpi = wsum(kpi);

    const float wr = 1.f + del * kpr, wi = del * kpi;
    const float iw = 1.f / (wr * wr + wi * wi);
    const float gar = del * wr * iw, gai = -del * wi * iw;
    const float dkr = del * kpr, dki = del * kpi;
    const float alr = del - (gar * dkr - gai * dki);
    const float ali = -(gar * dki + gai * dkr);

    #pragma unroll
    for (int s = 0; s < 2; ++s) {
        ur_[s] = alr * pr[s] + ali * pi[s] + gar * g_r[s] - gai * g_i[s];
        ui_[s] = -alr * pi[s] + ali * pr[s] + gar * g_i[s] + gai * g_r[s];
    }

    // per-m constants, scalar first
    float uEr[J][2], uEi[J][2], cEr[J][2], cEi[J][2], qEr[J][2], qEi[J][2];
    float eJr_[2], eJi_[2];
    {
        float emr[2] = {1.f, 1.f}, emi[2] = {0.f, 0.f};
        #pragma unroll
        for (int m = 0; m < J; ++m) {
            #pragma unroll
            for (int s = 0; s < 2; ++s) {
                uEr[m][s] = ur_[s] * emr[s] - ui_[s] * emi[s];
                uEi[m][s] = ur_[s] * emi[s] + ui_[s] * emr[s];
                cEr[m][s] = c2r[s] * emr[s] - c2i[s] * emi[s];
                cEi[m][s] = c2r[s] * emi[s] + c2i[s] * emr[s];
                qEr[m][s] = qr[s] * emr[s] - qi[s] * emi[s];
                qEi[m][s] = qr[s] * emi[s] + qi[s] * emr[s];
                const float t2 = emr[s] * er[s] - emi[s] * ei[s];
                emi[s] = emr[s] * ei[s] + emi[s] * er[s];
                emr[s] = t2;
            }
        }
        eJr_[0] = emr[0]; eJi_[0] = emi[0]; eJr_[1] = emr[1]; eJi_[1] = emi[1];
    }

    // scalars nu_m = u^T E^m q, eta_m = c2^T E^m q
    float nur[J], nui[J], etr[J], eti[J];
    #pragma unroll
    for (int m = 0; m < J; ++m) {
        float a = 0.f, b = 0.f, c = 0.f, d = 0.f;
        #pragma unroll
        for (int s = 0; s < 2; ++s) {
            a += ur_[s] * qEr[m][s] - ui_[s] * qEi[m][s];
            b += ur_[s] * qEi[m][s] + ui_[s] * qEr[m][s];
            c += c2r[s] * qEr[m][s] - c2i[s] * qEi[m][s];
            d += c2r[s] * qEi[m][s] + c2i[s] * qEr[m][s];
        }
        nur[m] = wsum(a); nui[m] = wsum(b);
        etr[m] = wsum(c); eti[m] = wsum(d);
    }

    // initial state x = dB via Woodbury
    float xr0[2], xi0[2];
    {
        float mmr[2], mmi[2];
        float taur = 0.f, taui = 0.f;
        #pragma unroll
        for (int s = 0; s < 2; ++s) {
            const int n = base + 32 * s;
            const float zr = dt * Br[n], zi = dt * Bi[n];
            mmr[s] = d_r[s] * zr - d_i[s] * zi;
            mmi[s] = d_r[s] * zi + d_i[s] * zr;
            taur += pr[s] * mmr[s] + pi[s] * mmi[s];
            taui += pr[s] * mmi[s] - pi[s] * mmr[s];
        }
        taur = wsum(taur); taui = wsum(taui);
        const float gtr = gar * taur - gai * taui;
        const float gti = gar * taui + gai * taur;
        #pragma unroll
        for (int s = 0; s < 2; ++s) {
            xr0[s] = mmr[s] - (gtr * qr[s] - gti * qi[s]);
            xi0[s] = mmi[s] - (gtr * qi[s] + gti * qr[s]);
        }
    }

    // ---- pack constants as float2 over slots ----
    float2 UEr[J], UEin[J], UEi[J], CEr[J], CEin[J], QErn[J], QEi_[J], QEin[J];
    #pragma unroll
    for (int m = 0; m < J; ++m) {
        UEr[m]  = f2(uEr[m][0], uEr[m][1]);
        UEin[m] = f2(-uEi[m][0], -uEi[m][1]);
        UEi[m]  = f2(uEi[m][0], uEi[m][1]);
        CEr[m]  = f2(cEr[m][0], cEr[m][1]);
        CEin[m] = f2(-cEi[m][0], -cEi[m][1]);
        QErn[m] = f2(-qEr[m][0], -qEr[m][1]);
        QEi_[m] = f2(qEi[m][0], qEi[m][1]);
        QEin[m] = f2(-qEi[m][0], -qEi[m][1]);
    }
    const float2 EJr  = f2(eJr_[0], eJr_[1]);
    const float2 EJi  = f2(eJi_[0], eJi_[1]);
    const float2 EJin = f2(-eJi_[0], -eJi_[1]);
    // recomb constants (only i = 0..J-2 used)
    float2 NURn[J], NUIpm[J];
    #pragma unroll
    for (int i = 0; i < J; ++i) {
        NURn[i]  = f2(-nur[i], -nur[i]);
        NUIpm[i] = f2(nui[i], -nui[i]);
    }

    float2 Xr = f2(xr0[0], xr0[1]);
    float2 Xi = f2(xi0[0], xi0[1]);

    float* __restrict__ o_ptr = out + (long)h * L;
    const int Lb = L & ~(J - 1);

    #pragma unroll 1
    for (int l = 0; l < Lb; l += J) {
        // packed dots: per m, pair over slots, then fold
        float mur[J], mui[J], kap[J];
        #pragma unroll
        for (int m = 0; m < J; ++m) {
            float2 mp = ffma2(UEin[m], Xi, fmul2(UEr[m], Xr));
            float2 ip = ffma2(UEi[m], Xr, fmul2(UEr[m], Xi));
            float2 kp = ffma2(CEin[m], Xi, fmul2(CEr[m], Xr));
            mur[m] = mp.x + mp.y;
            mui[m] = ip.x + ip.y;
            kap[m] = kp.x + kp.y;
        }

        // 6 packed butterfly trees: (mur_m,mui_m) x4, (kap0,kap1), (kap2,kap3)
        float2 T0 = f2(mur[0], mui[0]);
        float2 T1 = f2(mur[1], mui[1]);
        float2 T2 = f2(mur[2], mui[2]);
        float2 T3 = f2(mur[3], mui[3]);
        float2 T4 = f2(kap[0], kap[1]);
        float2 T5 = f2(kap[2], kap[3]);
        #pragma unroll
        for (int o = 16; o; o >>= 1) {
            T0 = fadd2(T0, f2(__shfl_xor_sync(0xffffffffu, T0.x, o),
                              __shfl_xor_sync(0xffffffffu, T0.y, o)));
            T1 = fadd2(T1, f2(__shfl_xor_sync(0xffffffffu, T1.x, o),
                              __shfl_xor_sync(0xffffffffu, T1.y, o)));
            T2 = fadd2(T2, f2(__shfl_xor_sync(0xffffffffu, T2.x, o),
                              __shfl_xor_sync(0xffffffffu, T2.y, o)));
            T3 = fadd2(T3, f2(__shfl_xor_sync(0xffffffffu, T3.x, o),
                              __shfl_xor_sync(0xffffffffu, T3.y, o)));
            T4 = fadd2(T4, f2(__shfl_xor_sync(0xffffffffu, T4.x, o),
                              __shfl_xor_sync(0xffffffffu, T4.y, o)));
            T5 = fadd2(T5, f2(__shfl_xor_sync(0xffffffffu, T5.x, o),
                              __shfl_xor_sync(0xffffffffu, T5.y, o)));
        }

        // recomb: t_m (packed re/im), k_m (scalar)
        float2 tP[J];
        float kk[J];
        {
            float2 M[J] = {T0, T1, T2, T3};
            float kz[J] = {T4.x, T4.y, T5.x, T5.y};
            #pragma unroll
            for (int m = 0; m < J; ++m) {
                float2 acc = M[m];
                float kv = kz[m];
                #pragma unroll
                for (int j = 0; j < m; ++j) {
                    const int i = m - 1 - j;
                    acc = ffma2(NURn[i], tP[j], acc);
                    acc = ffma2(NUIpm[i], f2(tP[j].y, tP[j].x), acc);
                    kv = fmaf(-etr[i], tP[j].x, fmaf(eti[i], tP[j].y, kv));
                }
                tP[m] = acc; kk[m] = kv;
            }
        }

        if (lane == 0) {
            float4 v = make_float4(kk[0], kk[1], kk[2], kk[3]);
            *reinterpret_cast<float4*>(o_ptr + l) = v;
        }

        // packed state update: x <- e^J.*x - sum_m t_m .* (E^{J-1-m} q)
        float2 NXr = ffma2(EJin, Xi, fmul2(EJr, Xr));
        float2 NXi = ffma2(EJi, Xr, fmul2(EJr, Xi));
        #pragma unroll
        for (int m = 0; m < J; ++m) {
            const int i = J - 1 - m;
            const float2 TrP = f2(tP[m].x, tP[m].x);
            const float2 TiP = f2(tP[m].y, tP[m].y);
            NXr = ffma2(QErn[i], TrP, ffma2(QEi_[i], TiP, NXr));
            NXi = ffma2(QErn[i], TiP, ffma2(QEin[i], TrP, NXi));
        }
        Xr = NXr; Xi = NXi;
    }

    // remainder (L not divisible by J) — scalar steps
    for (int l = Lb; l < L; ++l) {
        float sr = uEr[0][0] * Xr.x - uEi[0][0] * Xi.x
                 + uEr[0][1] * Xr.y - uEi[0][1] * Xi.y;
        float si = uEr[0][0] * Xi.x + uEi[0][0] * Xr.x
                 + uEr[0][1] * Xi.y + uEi[0][1] * Xr.y;
        float kv = cEr[0][0] * Xr.x - cEi[0][0] * Xi.x
                 + cEr[0][1] * Xr.y - cEi[0][1] * Xi.y;
        sr = wsum(sr); si = wsum(si); kv = wsum(kv);
        if (lane == 0) o_ptr[l] = kv;
        const float nx0r = er[0] * Xr.x - ei[0] * Xi.x - (sr * qr[0] - si * qi[0]);
        const float nx0i = er[0] * Xi.x + ei[0] * Xr.x - (sr * qi[0] + si * qr[0]);
        const float nx1r = er[1] * Xr.y - ei[1] * Xi.y - (sr * qr[1] - si * qi[1]);
        const float nx1i = er[1] * Xi.y + ei[1] * Xr.y - (sr * qi[1] + si * qr[1]);
        Xr = f2(nx0r, nx1r); Xi = f2(nx0i, nx1i);
    }
}

extern "C" void kernel_launch(void* const* d_in, const int* in_sizes, int n_in,
                              void* d_out, int out_size) {
    const float* Ar = (const float*)d_in[0];
    const float* Ai = (const float*)d_in[1];
    const float* Br = (const float*)d_in[2];
    const float* Bi = (const float*)d_in[3];
    const float* Pr = (const float*)d_in[4];
    const float* Pi = (const float*)d_in[5];
    const float* Cr = (const float*)d_in[6];
    const float* Ci = (const float*)d_in[7];
    const float* ld = (const float*)d_in[8];
    float* out = (float*)d_out;

    const int H = in_sizes[8];          // 256
    const int L = out_size / H;         // CH = 1 -> 2048

    const int warps_per_block = 2;
    const int blocks = (H + warps_per_block - 1) / warps_per_block;
    ssm_dplr_kernel<<<blocks, warps_per_block * 32>>>(
        Ar, Ai, Br, Bi, Pr, Pi, Cr, Ci, ld, out, H, L);
}

// round 5
// speedup vs baseline: 1.8957x; 1.0629x over previous
#include <cuda_runtime.h>

// S4/DPLR kernel materialization, H=256, N2=64, RANK=1, CH=1, L=2048.
// One warp per head (lane holds states n=lane, n=lane+32, packed as f32x2).
// T=8 blocked recurrence with LINEAR recombination: all in-block couplings
// folded into precomputed scalars (w) and packed vectors (R), so the serial
// path per block is dots -> one concurrent 24-tree reduction -> rank-8 update.

#define N2 64
#define T 8

typedef unsigned long long u64;

__device__ __forceinline__ float wsum(float v) {
    #pragma unroll
    for (int o = 16; o; o >>= 1) v += __shfl_xor_sync(0xffffffffu, v, o);
    return v;
}

__device__ __forceinline__ u64 pk(float x, float y) {
    u64 r; asm("mov.b64 %0,{%1,%2};" : "=l"(r) : "f"(x), "f"(y)); return r;
}
__device__ __forceinline__ float2 up(u64 a) {
    float2 v; asm("mov.b64 {%0,%1},%2;" : "=f"(v.x), "=f"(v.y) : "l"(a)); return v;
}
__device__ __forceinline__ u64 f2fma(u64 a, u64 b, u64 c) {
    u64 d; asm("fma.rn.f32x2 %0,%1,%2,%3;" : "=l"(d) : "l"(a), "l"(b), "l"(c)); return d;
}
__device__ __forceinline__ u64 f2mul(u64 a, u64 b) {
    u64 d; asm("mul.rn.f32x2 %0,%1,%2;" : "=l"(d) : "l"(a), "l"(b)); return d;
}

__global__ __launch_bounds__(64, 1) void ssm_dplr_kernel(
    const float* __restrict__ Ar, const float* __restrict__ Ai,
    const float* __restrict__ Br, const float* __restrict__ Bi,
    const float* __restrict__ Pr, const float* __restrict__ Pi,
    const float* __restrict__ Cr, const float* __restrict__ Ci,
    const float* __restrict__ logdt,
    float* __restrict__ out, int H, int L)
{
    const int h = blockIdx.x * (blockDim.x >> 5) + (threadIdx.x >> 5);
    if (h >= H) return;
    const int lane = threadIdx.x & 31;
    const int base = h * N2 + lane;

    const float dt  = expf(logdt[h]);
    const float del = 0.5f * dt;

    // ---- per-slot scalar setup ----
    float er[2], ei[2], qr[2], qi[2], ur_[2], ui_[2], c2r[2], c2i[2];
    float pr[2], pi[2], d_r[2], d_i[2], g_r[2], g_i[2];
    float mmr[2], mmi[2];

    float red4[4]; // kappa_r, kappa_i, tau_r, tau_i
    red4[0] = red4[1] = red4[2] = red4[3] = 0.f;
    #pragma unroll
    for (int s = 0; s < 2; ++s) {
        const int n = base + 32 * s;
        const float lr = -Ar[n], li = -Ai[n];
        const float ar = 1.f + del * lr, ai = del * li;
        const float mr = 1.f - del * lr, mi = -del * li;
        const float idm = 1.f / (mr * mr + mi * mi);
        d_r[s] = mr * idm; d_i[s] = -mi * idm;
        pr[s] = Pr[n]; pi[s] = Pi[n];
        er[s] = d_r[s] * ar - d_i[s] * ai;  ei[s] = d_r[s] * ai + d_i[s] * ar;
        qr[s] = d_r[s] * pr[s] - d_i[s] * pi[s];
        qi[s] = d_r[s] * pi[s] + d_i[s] * pr[s];
        g_r[s] = pr[s] * er[s] + pi[s] * ei[s];
        g_i[s] = pr[s] * ei[s] - pi[s] * er[s];
        c2r[s] = 2.f * Cr[n]; c2i[s] = 2.f * Ci[n];
        const float pp = pr[s] * pr[s] + pi[s] * pi[s];
        red4[0] += d_r[s] * pp; red4[1] += d_i[s] * pp;
        // dB pieces: mm = d .* (dt*B); tau = p^H mm
        const float zr = dt * Br[n], zi = dt * Bi[n];
        mmr[s] = d_r[s] * zr - d_i[s] * zi;
        mmi[s] = d_r[s] * zi + d_i[s] * zr;
        red4[2] += pr[s] * mmr[s] + pi[s] * mmi[s];
        red4[3] += pr[s] * mmi[s] - pi[s] * mmr[s];
    }
    #pragma unroll
    for (int o = 16; o; o >>= 1)
        #pragma unroll
        for (int k = 0; k < 4; ++k)
            red4[k] += __shfl_xor_sync(0xffffffffu, red4[k], o);
    const float kpr = red4[0], kpi = red4[1];
    const float taur = red4[2], taui = red4[3];

    const float wr0 = 1.f + del * kpr, wi0 = del * kpi;
    const float iw = 1.f / (wr0 * wr0 + wi0 * wi0);
    const float gar = del * wr0 * iw, gai = -del * wi0 * iw;
    const float dkr = del * kpr, dki = del * kpi;
    const float alr = del - (gar * dkr - gai * dki);
    const float ali = -(gar * dki + gai * dkr);

    #pragma unroll
    for (int s = 0; s < 2; ++s) {
        ur_[s] = alr * pr[s] + ali * pi[s] + gar * g_r[s] - gai * g_i[s];
        ui_[s] = -alr * pi[s] + ali * pr[s] + gar * g_i[s] + gai * g_r[s];
    }

    // initial state x = dB = mm - (gamma*tau).*q
    float xr0[2], xi0[2];
    {
        const float gtr = gar * taur - gai * taui;
        const float gti = gar * taui + gai * taur;
        #pragma unroll
        for (int s = 0; s < 2; ++s) {
            xr0[s] = mmr[s] - (gtr * qr[s] - gti * qi[s]);
            xi0[s] = mmi[s] - (gtr * qi[s] + gti * qr[s]);
        }
    }

    // ---- powers: qE_m = E^m q, uE_m = u.*e^m, cE_m = c2.*e^m, m=0..T-1; e^T ----
    float qer[T][2], qei[T][2], uer[T][2], uei[T][2], cer[T][2], cei[T][2];
    float e8r[2], e8i[2];
    {
        float emr[2] = {1.f, 1.f}, emi[2] = {0.f, 0.f};
        #pragma unroll
        for (int m = 0; m < T; ++m) {
            #pragma unroll
            for (int s = 0; s < 2; ++s) {
                qer[m][s] = qr[s] * emr[s] - qi[s] * emi[s];
                qei[m][s] = qr[s] * emi[s] + qi[s] * emr[s];
                uer[m][s] = ur_[s] * emr[s] - ui_[s] * emi[s];
                uei[m][s] = ur_[s] * emi[s] + ui_[s] * emr[s];
                cer[m][s] = c2r[s] * emr[s] - c2i[s] * emi[s];
                cei[m][s] = c2r[s] * emi[s] + c2i[s] * emr[s];
                const float t2 = emr[s] * er[s] - emi[s] * ei[s];
                emi[s] = emr[s] * ei[s] + emi[s] * er[s];
                emr[s] = t2;
            }
        }
        e8r[0] = emr[0]; e8i[0] = emi[0]; e8r[1] = emr[1]; e8i[1] = emi[1];
    }

    // ---- setup reductions: nu_m = u^T E^m q, eta_m = c2^T E^m q (m=0..T-2) ----
    float red[4 * (T - 1)];
    #pragma unroll
    for (int m = 0; m < T - 1; ++m) {
        float a = 0.f, b = 0.f, c = 0.f, d = 0.f;
        #pragma unroll
        for (int s = 0; s < 2; ++s) {
            a += ur_[s] * qer[m][s] - ui_[s] * qei[m][s];
            b += ur_[s] * qei[m][s] + ui_[s] * qer[m][s];
            c += c2r[s] * qer[m][s] - c2i[s] * qei[m][s];
            d += c2r[s] * qei[m][s] + c2i[s] * qer[m][s];
        }
        red[4 * m] = a; red[4 * m + 1] = b; red[4 * m + 2] = c; red[4 * m + 3] = d;
    }
    #pragma unroll
    for (int o = 16; o; o >>= 1)
        #pragma unroll
        for (int k = 0; k < 4 * (T - 1); ++k)
            red[k] += __shfl_xor_sync(0xffffffffu, red[k], o);

    float nur[T - 1], nui[T - 1], etr[T - 1], eti[T - 1];
    #pragma unroll
    for (int m = 0; m < T - 1; ++m) {
        nur[m] = red[4 * m];     nui[m] = red[4 * m + 1];
        etr[m] = red[4 * m + 2]; eti[m] = red[4 * m + 3];
    }

    // beta: power-series inverse of (1 + z*nu):  b0=1, b_m = -sum_{j<m} nu_{m-1-j} b_j
    float btr[T], bti[T];
    btr[0] = 1.f; bti[0] = 0.f;
    #pragma unroll
    for (int m = 1; m < T; ++m) {
        float a = 0.f, b = 0.f;
        #pragma unroll
        for (int j = 0; j < m; ++j) {
            a -= nur[m - 1 - j] * btr[j] - nui[m - 1 - j] * bti[j];
            b -= nur[m - 1 - j] * bti[j] + nui[m - 1 - j] * btr[j];
        }
        btr[m] = a; bti[m] = b;
    }
    // w = eta (*) beta :  w_m = sum_{a+b=m} eta_a beta_b   (m=0..T-2)
    float wcr[T - 1], wci[T - 1];
    #pragma unroll
    for (int m = 0; m < T - 1; ++m) {
        float a = 0.f, b = 0.f;
        #pragma unroll
        for (int j = 0; j <= m; ++j) {
            a += etr[j] * btr[m - j] - eti[j] * bti[m - j];
            b += etr[j] * bti[m - j] + eti[j] * btr[m - j];
        }
        wcr[m] = a; wci[m] = b;
    }

    // R_i = sum_{j=i..T-1} beta_{j-i} * qE_{T-1-j}  (complex, per slot)
    float rrr[T][2], rri[T][2];
    #pragma unroll
    for (int i = 0; i < T; ++i) {
        #pragma unroll
        for (int s = 0; s < 2; ++s) { rrr[i][s] = 0.f; rri[i][s] = 0.f; }
        #pragma unroll
        for (int j = i; j < T; ++j) {
            const float br2 = btr[j - i], bi2 = bti[j - i];
            #pragma unroll
            for (int s = 0; s < 2; ++s) {
                rrr[i][s] += br2 * qer[T - 1 - j][s] - bi2 * qei[T - 1 - j][s];
                rri[i][s] += br2 * qei[T - 1 - j][s] + bi2 * qer[T - 1 - j][s];
            }
        }
    }

    // ---- pack persistent packed constants ----
    u64 UEr[T], UEi[T], CEr[T], CEi[T], Rr[T], Ri[T];
    #pragma unroll
    for (int m = 0; m < T; ++m) {
        UEr[m] = pk(uer[m][0], uer[m][1]);
        UEi[m] = pk(uei[m][0], uei[m][1]);
        CEr[m] = pk(cer[m][0], cer[m][1]);
        CEi[m] = pk(cei[m][0], cei[m][1]);
        Rr[m]  = pk(rrr[m][0], rrr[m][1]);
        Ri[m]  = pk(rri[m][0], rri[m][1]);
    }
    const u64 E8r = pk(e8r[0], e8r[1]);
    const u64 E8i = pk(e8i[0], e8i[1]);
    const u64 NEG1 = pk(-1.f, -1.f);

    u64 Xr = pk(xr0[0], xr0[1]);
    u64 Xi = pk(xi0[0], xi0[1]);

    float* __restrict__ o_ptr = out + (long)h * L;
    const int Lb = L & ~(T - 1);

    #pragma unroll 1
    for (int l = 0; l < Lb; l += T) {
        const u64 XiN = f2mul(Xi, NEG1);

        // moments on block base state: mu_m (complex), kap_m (real)
        float mur[T], mui[T], kap[T];
        #pragma unroll
        for (int m = 0; m < T; ++m) {
            float2 a = up(f2fma(UEi[m], XiN, f2mul(UEr[m], Xr)));
            float2 b = up(f2fma(UEi[m], Xr,  f2mul(UEr[m], Xi)));
            float2 c = up(f2fma(CEi[m], XiN, f2mul(CEr[m], Xr)));
            mur[m] = a.x + a.y; mui[m] = b.x + b.y; kap[m] = c.x + c.y;
        }

        // 3T concurrent butterfly trees
        #pragma unroll
        for (int o = 16; o; o >>= 1) {
            #pragma unroll
            for (int m = 0; m < T; ++m) {
                mur[m] += __shfl_xor_sync(0xffffffffu, mur[m], o);
                mui[m] += __shfl_xor_sync(0xffffffffu, mui[m], o);
                kap[m] += __shfl_xor_sync(0xffffffffu, kap[m], o);
            }
        }

        // outputs: k_m = kap_m - sum_{i<m} Re(w_{m-1-i} * mu_i)  (pure FMAs)
        float kk[T];
        #pragma unroll
        for (int m = 0; m < T; ++m) {
            float kv = kap[m];
            #pragma unroll
            for (int i = 0; i < m; ++i) {
                const int d = m - 1 - i;
                kv = fmaf(-wcr[d], mur[i], fmaf(wci[d], mui[i], kv));
            }
            kk[m] = kv;
        }
        if (lane == 0) {
            *reinterpret_cast<float4*>(o_ptr + l)     = make_float4(kk[0], kk[1], kk[2], kk[3]);
            *reinterpret_cast<float4*>(o_ptr + l + 4) = make_float4(kk[4], kk[5], kk[6], kk[7]);
        }

        // state update: x' = e^T .* x - sum_i mu_i .* R_i
        u64 NXr = f2fma(E8i, XiN, f2mul(E8r, Xr));
        u64 NXi = f2fma(E8i, Xr,  f2mul(E8r, Xi));
        #pragma unroll
        for (int i = 0; i < T; ++i) {
            const u64 MrN = pk(-mur[i], -mur[i]);
            const u64 MiN = pk(-mui[i], -mui[i]);
            const u64 MiP = pk(mui[i], mui[i]);
            NXr = f2fma(MrN, Rr[i], f2fma(MiP, Ri[i], NXr));
            NXi = f2fma(MrN, Ri[i], f2fma(MiN, Rr[i], NXi));
        }
        Xr = NXr; Xi = NXi;
    }

    // remainder (L not divisible by T) — scalar steps
    for (int l = Lb; l < L; ++l) {
        float2 xr2 = up(Xr), xi2 = up(Xi);
        float xrr[2] = {xr2.x, xr2.y}, xii[2] = {xi2.x, xi2.y};
        float sr = 0.f, si = 0.f, kv = 0.f;
        #pragma unroll
        for (int s = 0; s < 2; ++s) {
            sr += ur_[s] * xrr[s] - ui_[s] * xii[s];
            si += ur_[s] * xii[s] + ui_[s] * xrr[s];
            kv += c2r[s] * xrr[s] - c2i[s] * xii[s];
        }
        sr = wsum(sr); si = wsum(si); kv = wsum(kv);
        if (lane == 0) o_ptr[l] = kv;
        float nxr[2], nxi[2];
        #pragma unroll
        for (int s = 0; s < 2; ++s) {
            nxr[s] = er[s] * xrr[s] - ei[s] * xii[s] - (sr * qr[s] - si * qi[s]);
            nxi[s] = er[s] * xii[s] + ei[s] * xrr[s] - (sr * qi[s] + si * qr[s]);
        }
        Xr = pk(nxr[0], nxr[1]); Xi = pk(nxi[0], nxi[1]);
    }
}

extern "C" void kernel_launch(void* const* d_in, const int* in_sizes, int n_in,
                              void* d_out, int out_size) {
    const float* Ar = (const float*)d_in[0];
    const float* Ai = (const float*)d_in[1];
    const float* Br = (const float*)d_in[2];
    const float* Bi = (const float*)d_in[3];
    const float* Pr = (const float*)d_in[4];
    const float* Pi = (const float*)d_in[5];
    const float* Cr = (const float*)d_in[6];
    const float* Ci = (const float*)d_in[7];
    const float* ld = (const float*)d_in[8];
    float* out = (float*)d_out;

    const int H = in_sizes[8];          // 256
    const int L = out_size / H;         // CH = 1 -> 2048

    const int warps_per_block = 2;
    const int blocks = (H + warps_per_block - 1) / warps_per_block;
    ssm_dplr_kernel<<<blocks, warps_per_block * 32>>>(
        Ar, Ai, Br, Bi, Pr, Pi, Cr, Ci, ld, out, H, L);
}

// round 6
// speedup vs baseline: 2.4784x; 1.3074x over previous
#include <cuda_runtime.h>

// S4/DPLR kernel materialization, H=256, N2=64, RANK=1, CH=1, L=2048.
// One warp per head (lane holds states n=lane, n=lane+32, packed as f32x2).
// T=8 blocked recurrence with linear recombination. This round: the 24
// per-block warp reductions go through a shared-memory transpose
// (scatter -> per-lane row sum -> broadcast) instead of shfl butterflies,
// because measured SHFL issue throughput is ~7 cyc/SHFL per warp (the wall
// in R3-R5).

#define N2 64
#define T 8

typedef unsigned long long u64;

__device__ __forceinline__ float wsum(float v) {
    #pragma unroll
    for (int o = 16; o; o >>= 1) v += __shfl_xor_sync(0xffffffffu, v, o);
    return v;
}

__device__ __forceinline__ u64 pk(float x, float y) {
    u64 r; asm("mov.b64 %0,{%1,%2};" : "=l"(r) : "f"(x), "f"(y)); return r;
}
__device__ __forceinline__ float2 up(u64 a) {
    float2 v; asm("mov.b64 {%0,%1},%2;" : "=f"(v.x), "=f"(v.y) : "l"(a)); return v;
}
__device__ __forceinline__ u64 f2fma(u64 a, u64 b, u64 c) {
    u64 d; asm("fma.rn.f32x2 %0,%1,%2,%3;" : "=l"(d) : "l"(a), "l"(b), "l"(c)); return d;
}
__device__ __forceinline__ u64 f2mul(u64 a, u64 b) {
    u64 d; asm("mul.rn.f32x2 %0,%1,%2;" : "=l"(d) : "l"(a), "l"(b)); return d;
}

#define ROWP 36  // padded row stride (floats): 144B, 16B-aligned, conflict-free

__global__ __launch_bounds__(64, 1) void ssm_dplr_kernel(
    const float* __restrict__ Ar, const float* __restrict__ Ai,
    const float* __restrict__ Br, const float* __restrict__ Bi,
    const float* __restrict__ Pr, const float* __restrict__ Pi,
    const float* __restrict__ Cr, const float* __restrict__ Ci,
    const float* __restrict__ logdt,
    float* __restrict__ out, int H, int L)
{
    __shared__ __align__(16) float s_part[2][24 * ROWP];
    __shared__ __align__(16) float s_res[2][32];

    const int h = blockIdx.x * (blockDim.x >> 5) + (threadIdx.x >> 5);
    if (h >= H) return;
    const int wip = threadIdx.x >> 5;
    const int lane = threadIdx.x & 31;
    const int base = h * N2 + lane;

    const float dt  = expf(logdt[h]);
    const float del = 0.5f * dt;

    // ---- per-slot scalar setup ----
    float er[2], ei[2], qr[2], qi[2], ur_[2], ui_[2], c2r[2], c2i[2];
    float pr[2], pi[2], d_r[2], d_i[2], g_r[2], g_i[2];
    float mmr[2], mmi[2];

    float red4[4]; // kappa_r, kappa_i, tau_r, tau_i
    red4[0] = red4[1] = red4[2] = red4[3] = 0.f;
    #pragma unroll
    for (int s = 0; s < 2; ++s) {
        const int n = base + 32 * s;
        const float lr = -Ar[n], li = -Ai[n];
        const float ar = 1.f + del * lr, ai = del * li;
        const float mr = 1.f - del * lr, mi = -del * li;
        const float idm = 1.f / (mr * mr + mi * mi);
        d_r[s] = mr * idm; d_i[s] = -mi * idm;
        pr[s] = Pr[n]; pi[s] = Pi[n];
        er[s] = d_r[s] * ar - d_i[s] * ai;  ei[s] = d_r[s] * ai + d_i[s] * ar;
        qr[s] = d_r[s] * pr[s] - d_i[s] * pi[s];
        qi[s] = d_r[s] * pi[s] + d_i[s] * pr[s];
        g_r[s] = pr[s] * er[s] + pi[s] * ei[s];
        g_i[s] = pr[s] * ei[s] - pi[s] * er[s];
        c2r[s] = 2.f * Cr[n]; c2i[s] = 2.f * Ci[n];
        const float pp = pr[s] * pr[s] + pi[s] * pi[s];
        red4[0] += d_r[s] * pp; red4[1] += d_i[s] * pp;
        const float zr = dt * Br[n], zi = dt * Bi[n];
        mmr[s] = d_r[s] * zr - d_i[s] * zi;
        mmi[s] = d_r[s] * zi + d_i[s] * zr;
        red4[2] += pr[s] * mmr[s] + pi[s] * mmi[s];
        red4[3] += pr[s] * mmi[s] - pi[s] * mmr[s];
    }
    #pragma unroll
    for (int o = 16; o; o >>= 1)
        #pragma unroll
        for (int k = 0; k < 4; ++k)
            red4[k] += __shfl_xor_sync(0xffffffffu, red4[k], o);
    const float kpr = red4[0], kpi = red4[1];
    const float taur = red4[2], taui = red4[3];

    const float wr0 = 1.f + del * kpr, wi0 = del * kpi;
    const float iw = 1.f / (wr0 * wr0 + wi0 * wi0);
    const float gar = del * wr0 * iw, gai = -del * wi0 * iw;
    const float dkr = del * kpr, dki = del * kpi;
    const float alr = del - (gar * dkr - gai * dki);
    const float ali = -(gar * dki + gai * dkr);

    #pragma unroll
    for (int s = 0; s < 2; ++s) {
        ur_[s] = alr * pr[s] + ali * pi[s] + gar * g_r[s] - gai * g_i[s];
        ui_[s] = -alr * pi[s] + ali * pr[s] + gar * g_i[s] + gai * g_r[s];
    }

    // initial state x = dB = mm - (gamma*tau).*q
    float xr0[2], xi0[2];
    {
        const float gtr = gar * taur - gai * taui;
        const float gti = gar * taui + gai * taur;
        #pragma unroll
        for (int s = 0; s < 2; ++s) {
            xr0[s] = mmr[s] - (gtr * qr[s] - gti * qi[s]);
            xi0[s] = mmi[s] - (gtr * qi[s] + gti * qr[s]);
        }
    }

    // ---- powers: qE_m = E^m q, uE_m = u.*e^m, cE_m = c2.*e^m, m=0..T-1; e^T ----
    float qer[T][2], qei[T][2], uer[T][2], uei[T][2], cer[T][2], cei[T][2];
    float e8r[2], e8i[2];
    {
        float emr[2] = {1.f, 1.f}, emi[2] = {0.f, 0.f};
        #pragma unroll
        for (int m = 0; m < T; ++m) {
            #pragma unroll
            for (int s = 0; s < 2; ++s) {
                qer[m][s] = qr[s] * emr[s] - qi[s] * emi[s];
                qei[m][s] = qr[s] * emi[s] + qi[s] * emr[s];
                uer[m][s] = ur_[s] * emr[s] - ui_[s] * emi[s];
                uei[m][s] = ur_[s] * emi[s] + ui_[s] * emr[s];
                cer[m][s] = c2r[s] * emr[s] - c2i[s] * emi[s];
                cei[m][s] = c2r[s] * emi[s] + c2i[s] * emr[s];
                const float t2 = emr[s] * er[s] - emi[s] * ei[s];
                emi[s] = emr[s] * ei[s] + emi[s] * er[s];
                emr[s] = t2;
            }
        }
        e8r[0] = emr[0]; e8i[0] = emi[0]; e8r[1] = emr[1]; e8i[1] = emi[1];
    }

    // ---- setup reductions: nu_m = u^T E^m q, eta_m = c2^T E^m q (m=0..T-2) ----
    float red[4 * (T - 1)];
    #pragma unroll
    for (int m = 0; m < T - 1; ++m) {
        float a = 0.f, b = 0.f, c = 0.f, d = 0.f;
        #pragma unroll
        for (int s = 0; s < 2; ++s) {
            a += ur_[s] * qer[m][s] - ui_[s] * qei[m][s];
            b += ur_[s] * qei[m][s] + ui_[s] * qer[m][s];
            c += c2r[s] * qer[m][s] - c2i[s] * qei[m][s];
            d += c2r[s] * qei[m][s] + c2i[s] * qer[m][s];
        }
        red[4 * m] = a; red[4 * m + 1] = b; red[4 * m + 2] = c; red[4 * m + 3] = d;
    }
    #pragma unroll
    for (int o = 16; o; o >>= 1)
        #pragma unroll
        for (int k = 0; k < 4 * (T - 1); ++k)
            red[k] += __shfl_xor_sync(0xffffffffu, red[k], o);

    float nur[T - 1], nui[T - 1], etr[T - 1], eti[T - 1];
    #pragma unroll
    for (int m = 0; m < T - 1; ++m) {
        nur[m] = red[4 * m];     nui[m] = red[4 * m + 1];
        etr[m] = red[4 * m + 2]; eti[m] = red[4 * m + 3];
    }

    // beta = power-series inverse of (1 + z*nu)
    float btr[T], bti[T];
    btr[0] = 1.f; bti[0] = 0.f;
    #pragma unroll
    for (int m = 1; m < T; ++m) {
        float a = 0.f, b = 0.f;
        #pragma unroll
        for (int j = 0; j < m; ++j) {
            a -= nur[m - 1 - j] * btr[j] - nui[m - 1 - j] * bti[j];
            b -= nur[m - 1 - j] * bti[j] + nui[m - 1 - j] * btr[j];
        }
        btr[m] = a; bti[m] = b;
    }
    // w = eta (*) beta
    float wcr[T - 1], wci[T - 1];
    #pragma unroll
    for (int m = 0; m < T - 1; ++m) {
        float a = 0.f, b = 0.f;
        #pragma unroll
        for (int j = 0; j <= m; ++j) {
            a += etr[j] * btr[m - j] - eti[j] * bti[m - j];
            b += etr[j] * bti[m - j] + eti[j] * btr[m - j];
        }
        wcr[m] = a; wci[m] = b;
    }

    // R_i = sum_{j=i..T-1} beta_{j-i} * qE_{T-1-j}
    float rrr[T][2], rri[T][2];
    #pragma unroll
    for (int i = 0; i < T; ++i) {
        #pragma unroll
        for (int s = 0; s < 2; ++s) { rrr[i][s] = 0.f; rri[i][s] = 0.f; }
        #pragma unroll
        for (int j = i; j < T; ++j) {
            const float br2 = btr[j - i], bi2 = bti[j - i];
            #pragma unroll
            for (int s = 0; s < 2; ++s) {
                rrr[i][s] += br2 * qer[T - 1 - j][s] - bi2 * qei[T - 1 - j][s];
                rri[i][s] += br2 * qei[T - 1 - j][s] + bi2 * qer[T - 1 - j][s];
            }
        }
    }

    // ---- pack persistent packed constants ----
    u64 UEr[T], UEi[T], CEr[T], CEi[T], Rr[T], Ri[T];
    #pragma unroll
    for (int m = 0; m < T; ++m) {
        UEr[m] = pk(uer[m][0], uer[m][1]);
        UEi[m] = pk(uei[m][0], uei[m][1]);
        CEr[m] = pk(cer[m][0], cer[m][1]);
        CEi[m] = pk(cei[m][0], cei[m][1]);
        Rr[m]  = pk(rrr[m][0], rrr[m][1]);
        Ri[m]  = pk(rri[m][0], rri[m][1]);
    }
    const u64 E8r = pk(e8r[0], e8r[1]);
    const u64 E8i = pk(e8i[0], e8i[1]);
    const u64 NEG1 = pk(-1.f, -1.f);

    u64 Xr = pk(xr0[0], xr0[1]);
    u64 Xi = pk(xi0[0], xi0[1]);

    float* __restrict__ o_ptr = out + (long)h * L;
    const int Lb = L & ~(T - 1);

    float* const sp  = &s_part[wip][0];
    float* const sr_ = &s_res[wip][0];

    #pragma unroll 1
    for (int l = 0; l < Lb; l += T) {
        const u64 XiN = f2mul(Xi, NEG1);

        // dots -> scatter partials to smem rows
        // row index: m -> mur, 8+m -> mui, 16+m -> kap
        #pragma unroll
        for (int m = 0; m < T; ++m) {
            float2 a = up(f2fma(UEi[m], XiN, f2mul(UEr[m], Xr)));
            float2 b = up(f2fma(UEi[m], Xr,  f2mul(UEr[m], Xi)));
            float2 c = up(f2fma(CEi[m], XiN, f2mul(CEr[m], Xr)));
            sp[m * ROWP + lane]        = a.x + a.y;
            sp[(8 + m) * ROWP + lane]  = b.x + b.y;
            sp[(16 + m) * ROWP + lane] = c.x + c.y;
        }
        __syncwarp();

        // lanes 0..23: sum one row (8 x LDS.128, 31 FADD), write result
        if (lane < 24) {
            const float4* row = reinterpret_cast<const float4*>(sp + lane * ROWP);
            float4 v0 = row[0], v1 = row[1], v2 = row[2], v3 = row[3];
            float4 v4 = row[4], v5 = row[5], v6 = row[6], v7 = row[7];
            float4 t0 = make_float4(v0.x + v4.x, v0.y + v4.y, v0.z + v4.z, v0.w + v4.w);
            float4 t1 = make_float4(v1.x + v5.x, v1.y + v5.y, v1.z + v5.z, v1.w + v5.w);
            float4 t2 = make_float4(v2.x + v6.x, v2.y + v6.y, v2.z + v6.z, v2.w + v6.w);
            float4 t3 = make_float4(v3.x + v7.x, v3.y + v7.y, v3.z + v7.z, v3.w + v7.w);
            float4 u0 = make_float4(t0.x + t2.x, t0.y + t2.y, t0.z + t2.z, t0.w + t2.w);
            float4 u1 = make_float4(t1.x + t3.x, t1.y + t3.y, t1.z + t3.z, t1.w + t3.w);
            float4 ww = make_float4(u0.x + u1.x, u0.y + u1.y, u0.z + u1.z, u0.w + u1.w);
            sr_[lane] = (ww.x + ww.y) + (ww.z + ww.w);
        }
        __syncwarp();

        // broadcast mu (static-indexed), lanes 0..7 do outputs via dynamic LDS
        const float4 m0 = *reinterpret_cast<const float4*>(sr_ + 0);
        const float4 m1 = *reinterpret_cast<const float4*>(sr_ + 4);
        const float4 n0 = *reinterpret_cast<const float4*>(sr_ + 8);
        const float4 n1 = *reinterpret_cast<const float4*>(sr_ + 12);
        const float mur[T] = {m0.x, m0.y, m0.z, m0.w, m1.x, m1.y, m1.z, m1.w};
        const float mui[T] = {n0.x, n0.y, n0.z, n0.w, n1.x, n1.y, n1.z, n1.w};

        if (lane < 8) {
            float kv = sr_[16 + lane];
            #pragma unroll
            for (int d = 0; d < 7; ++d) {
                if (d < lane) {
                    const int idx = lane - 1 - d;
                    kv = fmaf(-wcr[d], sr_[idx], fmaf(wci[d], sr_[8 + idx], kv));
                }
            }
            o_ptr[l + lane] = kv;
        }

        // state update: x' = e^T .* x - sum_i mu_i .* R_i
        u64 NXr = f2fma(E8i, XiN, f2mul(E8r, Xr));
        u64 NXi = f2fma(E8i, Xr,  f2mul(E8r, Xi));
        #pragma unroll
        for (int i = 0; i < T; ++i) {
            const u64 A = pk(-mur[i], -mur[i]);
            const u64 B = pk(mui[i], mui[i]);
            const u64 C = pk(-mui[i], -mui[i]);
            NXr = f2fma(A, Rr[i], f2fma(B, Ri[i], NXr));
            NXi = f2fma(A, Ri[i], f2fma(C, Rr[i], NXi));
        }
        Xr = NXr; Xi = NXi;
    }

    // remainder (L not divisible by T) — scalar steps (cold; L=2048 -> unused)
    for (int l = Lb; l < L; ++l) {
        float2 xr2 = up(Xr), xi2 = up(Xi);
        float xrr[2] = {xr2.x, xr2.y}, xii[2] = {xi2.x, xi2.y};
        float sr2 = 0.f, si2 = 0.f, kv = 0.f;
        #pragma unroll
        for (int s = 0; s < 2; ++s) {
            sr2 += ur_[s] * xrr[s] - ui_[s] * xii[s];
            si2 += ur_[s] * xii[s] + ui_[s] * xrr[s];
            kv  += c2r[s] * xrr[s] - c2i[s] * xii[s];
        }
        sr2 = wsum(sr2); si2 = wsum(si2); kv = wsum(kv);
        if (lane == 0) o_ptr[l] = kv;
        float nxr[2], nxi[2];
        #pragma unroll
        for (int s = 0; s < 2; ++s) {
            nxr[s] = er[s] * xrr[s] - ei[s] * xii[s] - (sr2 * qr[s] - si2 * qi[s]);
            nxi[s] = er[s] * xii[s] + ei[s] * xrr[s] - (sr2 * qi[s] + si2 * qr[s]);
        }
        Xr = pk(nxr[0], nxr[1]); Xi = pk(nxi[0], nxi[1]);
    }
}

extern "C" void kernel_launch(void* const* d_in, const int* in_sizes, int n_in,
                              void* d_out, int out_size) {
    const float* Ar = (const float*)d_in[0];
    const float* Ai = (const float*)d_in[1];
    const float* Br = (const float*)d_in[2];
    const float* Bi = (const float*)d_in[3];
    const float* Pr = (const float*)d_in[4];
    const float* Pi = (const float*)d_in[5];
    const float* Cr = (const float*)d_in[6];
    const float* Ci = (const float*)d_in[7];
    const float* ld = (const float*)d_in[8];
    float* out = (float*)d_out;

    const int H = in_sizes[8];          // 256
    const int L = out_size / H;         // CH = 1 -> 2048

    const int warps_per_block = 2;
    const int blocks = (H + warps_per_block - 1) / warps_per_block;
    ssm_dplr_kernel<<<blocks, warps_per_block * 32>>>(
        Ar, Ai, Br, Bi, Pr, Pi, Cr, Ci, ld, out, H, L);
}

// round 7
// speedup vs baseline: 3.1050x; 1.2528x over previous
#include <cuda_runtime.h>

// S4/DPLR kernel materialization, H=256, N2=64, RANK=1, CH=1, L=2048.
// One warp per head (lane holds states n=lane, n=lane+32, packed as f32x2).
// T=8 blocked recurrence, linear recombination, smem-transpose reductions.
// This round: fully branchless hot loop (duplicate row-sums for lanes 24-31,
// per-lane premasked conv coefficients, predicated store) and a split
// (2-chain) rank-8 state update to cut dependency depth.

#define N2 64
#define T 8

typedef unsigned long long u64;

__device__ __forceinline__ float wsum(float v) {
    #pragma unroll
    for (int o = 16; o; o >>= 1) v += __shfl_xor_sync(0xffffffffu, v, o);
    return v;
}

__device__ __forceinline__ u64 pk(float x, float y) {
    u64 r; asm("mov.b64 %0,{%1,%2};" : "=l"(r) : "f"(x), "f"(y)); return r;
}
__device__ __forceinline__ float2 up(u64 a) {
    float2 v; asm("mov.b64 {%0,%1},%2;" : "=f"(v.x), "=f"(v.y) : "l"(a)); return v;
}
__device__ __forceinline__ u64 f2fma(u64 a, u64 b, u64 c) {
    u64 d; asm("fma.rn.f32x2 %0,%1,%2,%3;" : "=l"(d) : "l"(a), "l"(b), "l"(c)); return d;
}
__device__ __forceinline__ u64 f2mul(u64 a, u64 b) {
    u64 d; asm("mul.rn.f32x2 %0,%1,%2;" : "=l"(d) : "l"(a), "l"(b)); return d;
}
__device__ __forceinline__ u64 f2add(u64 a, u64 b) {
    u64 d; asm("add.rn.f32x2 %0,%1,%2;" : "=l"(d) : "l"(a), "l"(b)); return d;
}

#define ROWP 36  // padded row stride (floats): conflict-free for float4 loads

__global__ __launch_bounds__(64, 1) void ssm_dplr_kernel(
    const float* __restrict__ Ar, const float* __restrict__ Ai,
    const float* __restrict__ Br, const float* __restrict__ Bi,
    const float* __restrict__ Pr, const float* __restrict__ Pi,
    const float* __restrict__ Cr, const float* __restrict__ Ci,
    const float* __restrict__ logdt,
    float* __restrict__ out, int H, int L)
{
    __shared__ __align__(16) float s_part[2][24 * ROWP];
    __shared__ __align__(16) float s_res[2][32];

    const int h = blockIdx.x * (blockDim.x >> 5) + (threadIdx.x >> 5);
    if (h >= H) return;
    const int wip = threadIdx.x >> 5;
    const int lane = threadIdx.x & 31;
    const int base = h * N2 + lane;

    const float dt  = expf(logdt[h]);
    const float del = 0.5f * dt;

    // ---- per-slot scalar setup ----
    float er[2], ei[2], qr[2], qi[2], ur_[2], ui_[2], c2r[2], c2i[2];
    float pr[2], pi[2], d_r[2], d_i[2];
    float mmr[2], mmi[2];

    float red4[4]; // kappa_r, kappa_i, tau_r, tau_i
    red4[0] = red4[1] = red4[2] = red4[3] = 0.f;
    #pragma unroll
    for (int s = 0; s < 2; ++s) {
        const int n = base + 32 * s;
        const float lr = -Ar[n], li = -Ai[n];
        const float ar = 1.f + del * lr, ai = del * li;
        const float mr = 1.f - del * lr, mi = -del * li;
        const float idm = 1.f / (mr * mr + mi * mi);
        d_r[s] = mr * idm; d_i[s] = -mi * idm;
        pr[s] = Pr[n]; pi[s] = Pi[n];
        er[s] = d_r[s] * ar - d_i[s] * ai;  ei[s] = d_r[s] * ai + d_i[s] * ar;
        qr[s] = d_r[s] * pr[s] - d_i[s] * pi[s];
        qi[s] = d_r[s] * pi[s] + d_i[s] * pr[s];
        c2r[s] = 2.f * Cr[n]; c2i[s] = 2.f * Ci[n];
        const float pp = pr[s] * pr[s] + pi[s] * pi[s];
        red4[0] += d_r[s] * pp; red4[1] += d_i[s] * pp;
        const float zr = dt * Br[n], zi = dt * Bi[n];
        mmr[s] = d_r[s] * zr - d_i[s] * zi;
        mmi[s] = d_r[s] * zi + d_i[s] * zr;
        red4[2] += pr[s] * mmr[s] + pi[s] * mmi[s];
        red4[3] += pr[s] * mmi[s] - pi[s] * mmr[s];
    }
    #pragma unroll
    for (int o = 16; o; o >>= 1)
        #pragma unroll
        for (int k = 0; k < 4; ++k)
            red4[k] += __shfl_xor_sync(0xffffffffu, red4[k], o);
    const float kpr = red4[0], kpi = red4[1];
    const float taur = red4[2], taui = red4[3];

    const float wr0 = 1.f + del * kpr, wi0 = del * kpi;
    const float iw = 1.f / (wr0 * wr0 + wi0 * wi0);
    const float gar = del * wr0 * iw, gai = -del * wi0 * iw;
    const float dkr = del * kpr, dki = del * kpi;
    const float alr = del - (gar * dkr - gai * dki);
    const float ali = -(gar * dki + gai * dkr);

    #pragma unroll
    for (int s = 0; s < 2; ++s) {
        const float gr2 = pr[s] * er[s] + pi[s] * ei[s];
        const float gi2 = pr[s] * ei[s] - pi[s] * er[s];
        ur_[s] = alr * pr[s] + ali * pi[s] + gar * gr2 - gai * gi2;
        ui_[s] = -alr * pi[s] + ali * pr[s] + gar * gi2 + gai * gr2;
    }

    // initial state x = dB = mm - (gamma*tau).*q
    float xr0[2], xi0[2];
    {
        const float gtr = gar * taur - gai * taui;
        const float gti = gar * taui + gai * taur;
        #pragma unroll
        for (int s = 0; s < 2; ++s) {
            xr0[s] = mmr[s] - (gtr * qr[s] - gti * qi[s]);
            xi0[s] = mmi[s] - (gtr * qi[s] + gti * qr[s]);
        }
    }

    // ---- powers: qE_m = E^m q, uE_m = u.*e^m, cE_m = c2.*e^m, m=0..T-1; e^T ----
    float qer[T][2], qei[T][2], uer[T][2], uei[T][2], cer[T][2], cei[T][2];
    float e8r[2], e8i[2];
    {
        float emr[2] = {1.f, 1.f}, emi[2] = {0.f, 0.f};
        #pragma unroll
        for (int m = 0; m < T; ++m) {
            #pragma unroll
            for (int s = 0; s < 2; ++s) {
                qer[m][s] = qr[s] * emr[s] - qi[s] * emi[s];
                qei[m][s] = qr[s] * emi[s] + qi[s] * emr[s];
                uer[m][s] = ur_[s] * emr[s] - ui_[s] * emi[s];
                uei[m][s] = ur_[s] * emi[s] + ui_[s] * emr[s];
                cer[m][s] = c2r[s] * emr[s] - c2i[s] * emi[s];
                cei[m][s] = c2r[s] * emi[s] + c2i[s] * emr[s];
                const float t2 = emr[s] * er[s] - emi[s] * ei[s];
                emi[s] = emr[s] * ei[s] + emi[s] * er[s];
                emr[s] = t2;
            }
        }
        e8r[0] = emr[0]; e8i[0] = emi[0]; e8r[1] = emr[1]; e8i[1] = emi[1];
    }

    // ---- setup reductions: nu_m = u^T E^m q, eta_m = c2^T E^m q (m=0..T-2) ----
    float red[4 * (T - 1)];
    #pragma unroll
    for (int m = 0; m < T - 1; ++m) {
        float a = 0.f, b = 0.f, c = 0.f, d = 0.f;
        #pragma unroll
        for (int s = 0; s < 2; ++s) {
            a += ur_[s] * qer[m][s] - ui_[s] * qei[m][s];
            b += ur_[s] * qei[m][s] + ui_[s] * qer[m][s];
            c += c2r[s] * qer[m][s] - c2i[s] * qei[m][s];
            d += c2r[s] * qei[m][s] + c2i[s] * qer[m][s];
        }
        red[4 * m] = a; red[4 * m + 1] = b; red[4 * m + 2] = c; red[4 * m + 3] = d;
    }
    #pragma unroll
    for (int o = 16; o; o >>= 1)
        #pragma unroll
        for (int k = 0; k < 4 * (T - 1); ++k)
            red[k] += __shfl_xor_sync(0xffffffffu, red[k], o);

    float nur[T - 1], nui[T - 1], etr[T - 1], eti[T - 1];
    #pragma unroll
    for (int m = 0; m < T - 1; ++m) {
        nur[m] = red[4 * m];     nui[m] = red[4 * m + 1];
        etr[m] = red[4 * m + 2]; eti[m] = red[4 * m + 3];
    }

    // beta = power-series inverse of (1 + z*nu)
    float btr[T], bti[T];
    btr[0] = 1.f; bti[0] = 0.f;
    #pragma unroll
    for (int m = 1; m < T; ++m) {
        float a = 0.f, b = 0.f;
        #pragma unroll
        for (int j = 0; j < m; ++j) {
            a -= nur[m - 1 - j] * btr[j] - nui[m - 1 - j] * bti[j];
            b -= nur[m - 1 - j] * bti[j] + nui[m - 1 - j] * btr[j];
        }
        btr[m] = a; bti[m] = b;
    }
    // w = eta (*) beta
    float wcr[T - 1], wci[T - 1];
    #pragma unroll
    for (int m = 0; m < T - 1; ++m) {
        float a = 0.f, b = 0.f;
        #pragma unroll
        for (int j = 0; j <= m; ++j) {
            a += etr[j] * btr[m - j] - eti[j] * bti[m - j];
            b += etr[j] * bti[m - j] + eti[j] * btr[m - j];
        }
        wcr[m] = a; wci[m] = b;
    }

    // R_i = sum_{j=i..T-1} beta_{j-i} * qE_{T-1-j}
    float rrr[T][2], rri[T][2];
    #pragma unroll
    for (int i = 0; i < T; ++i) {
        #pragma unroll
        for (int s = 0; s < 2; ++s) { rrr[i][s] = 0.f; rri[i][s] = 0.f; }
        #pragma unroll
        for (int j = i; j < T; ++j) {
            const float br2 = btr[j - i], bi2 = bti[j - i];
            #pragma unroll
            for (int s = 0; s < 2; ++s) {
                rrr[i][s] += br2 * qer[T - 1 - j][s] - bi2 * qei[T - 1 - j][s];
                rri[i][s] += br2 * qei[T - 1 - j][s] + bi2 * qer[T - 1 - j][s];
            }
        }
    }

    // ---- pack persistent packed constants ----
    u64 UEr[T], UEi[T], CEr[T], CEi[T], Rr[T], Ri[T];
    #pragma unroll
    for (int m = 0; m < T; ++m) {
        UEr[m] = pk(uer[m][0], uer[m][1]);
        UEi[m] = pk(uei[m][0], uei[m][1]);
        CEr[m] = pk(cer[m][0], cer[m][1]);
        CEi[m] = pk(cei[m][0], cei[m][1]);
        Rr[m]  = pk(rrr[m][0], rrr[m][1]);
        Ri[m]  = pk(rri[m][0], rri[m][1]);
    }
    const u64 E8r = pk(e8r[0], e8r[1]);
    const u64 E8i = pk(e8i[0], e8i[1]);
    const u64 NEG1 = pk(-1.f, -1.f);
    const u64 ZERO = pk(0.f, 0.f);

    u64 Xr = pk(xr0[0], xr0[1]);
    u64 Xi = pk(xi0[0], xi0[1]);

    float* __restrict__ o_ptr = out + (long)h * L;
    const int Lb = L & ~(T - 1);

    float* const sp  = &s_part[wip][0];
    float* const sr_ = &s_res[wip][0];

    // branchless row assignment: lanes 24-31 duplicate rows 0-7 (harmless)
    const int row = (lane >= 24) ? (lane - 24) : lane;
    const float4* const rowp = reinterpret_cast<const float4*>(sp + row * ROWP);

    // per-lane premasked conv coefficients (lane handles output m = lane & 7)
    const int mo = lane & 7;
    float mwr[T - 1], mwi[T - 1];
    int mix0[T - 1], mix1[T - 1];
    #pragma unroll
    for (int d = 0; d < T - 1; ++d) {
        const bool act = d < mo;
        const int idx = act ? (mo - 1 - d) : 0;
        mwr[d] = act ? -wcr[d] : 0.f;
        mwi[d] = act ? wci[d] : 0.f;
        mix0[d] = idx;
        mix1[d] = 8 + idx;
    }
    const bool do_store = (lane < 8);

    #pragma unroll 1
    for (int l = 0; l < Lb; l += T) {
        const u64 XiN = f2mul(Xi, NEG1);

        // dots -> scatter partials: rows m -> mur, 8+m -> mui, 16+m -> kap
        #pragma unroll
        for (int m = 0; m < T; ++m) {
            float2 a = up(f2fma(UEi[m], XiN, f2mul(UEr[m], Xr)));
            float2 b = up(f2fma(UEi[m], Xr,  f2mul(UEr[m], Xi)));
            float2 c = up(f2fma(CEi[m], XiN, f2mul(CEr[m], Xr)));
            sp[m * ROWP + lane]        = a.x + a.y;
            sp[(8 + m) * ROWP + lane]  = b.x + b.y;
            sp[(16 + m) * ROWP + lane] = c.x + c.y;
        }
        __syncwarp();

        // all 32 lanes sum a row (lanes 24-31 duplicate rows 0-7)
        {
            float4 v0 = rowp[0], v1 = rowp[1], v2 = rowp[2], v3 = rowp[3];
            float4 v4 = rowp[4], v5 = rowp[5], v6 = rowp[6], v7 = rowp[7];
            float4 t0 = make_float4(v0.x + v4.x, v0.y + v4.y, v0.z + v4.z, v0.w + v4.w);
            float4 t1 = make_float4(v1.x + v5.x, v1.y + v5.y, v1.z + v5.z, v1.w + v5.w);
            float4 t2 = make_float4(v2.x + v6.x, v2.y + v6.y, v2.z + v6.z, v2.w + v6.w);
            float4 t3 = make_float4(v3.x + v7.x, v3.y + v7.y, v3.z + v7.z, v3.w + v7.w);
            float4 u0 = make_float4(t0.x + t2.x, t0.y + t2.y, t0.z + t2.z, t0.w + t2.w);
            float4 u1 = make_float4(t1.x + t3.x, t1.y + t3.y, t1.z + t3.z, t1.w + t3.w);
            float4 ww = make_float4(u0.x + u1.x, u0.y + u1.y, u0.z + u1.z, u0.w + u1.w);
            sr_[lane] = (ww.x + ww.y) + (ww.z + ww.w);
        }
        __syncwarp();

        // broadcast mu (uniform-address LDS)
        const float4 m0 = *reinterpret_cast<const float4*>(sr_ + 0);
        const float4 m1 = *reinterpret_cast<const float4*>(sr_ + 4);
        const float4 n0 = *reinterpret_cast<const float4*>(sr_ + 8);
        const float4 n1 = *reinterpret_cast<const float4*>(sr_ + 12);
        const float mur[T] = {m0.x, m0.y, m0.z, m0.w, m1.x, m1.y, m1.z, m1.w};
        const float mui[T] = {n0.x, n0.y, n0.z, n0.w, n1.x, n1.y, n1.z, n1.w};

        // state update, two accumulator chains (even/odd i)
        {
            u64 A0 = f2fma(E8i, XiN, f2mul(E8r, Xr));
            u64 B0 = f2fma(E8i, Xr,  f2mul(E8r, Xi));
            u64 A1 = ZERO, B1 = ZERO;
            #pragma unroll
            for (int i = 0; i < T; i += 2) {
                const u64 a0 = pk(-mur[i], -mur[i]);
                const u64 b0 = pk(mui[i], mui[i]);
                const u64 c0 = pk(-mui[i], -mui[i]);
                A0 = f2fma(a0, Rr[i], f2fma(b0, Ri[i], A0));
                B0 = f2fma(a0, Ri[i], f2fma(c0, Rr[i], B0));
                const u64 a1 = pk(-mur[i + 1], -mur[i + 1]);
                const u64 b1 = pk(mui[i + 1], mui[i + 1]);
                const u64 c1 = pk(-mui[i + 1], -mui[i + 1]);
                A1 = f2fma(a1, Rr[i + 1], f2fma(b1, Ri[i + 1], A1));
                B1 = f2fma(a1, Ri[i + 1], f2fma(c1, Rr[i + 1], B1));
            }
            Xr = f2add(A0, A1);
            Xi = f2add(B0, B1);
        }

        // outputs: branchless masked conv, predicated store
        {
            float kv = sr_[16 + mo];
            #pragma unroll
            for (int d = 0; d < T - 1; ++d)
                kv = fmaf(mwr[d], sr_[mix0[d]], fmaf(mwi[d], sr_[mix1[d]], kv));
            if (do_store) o_ptr[l + mo] = kv;
        }
    }

    // remainder (L not divisible by T) — scalar steps (cold; L=2048 -> unused)
    for (int l = Lb; l < L; ++l) {
        float2 xr2 = up(Xr), xi2 = up(Xi);
        float xrr[2] = {xr2.x, xr2.y}, xii[2] = {xi2.x, xi2.y};
        float sr2 = 0.f, si2 = 0.f, kv = 0.f;
        #pragma unroll
        for (int s = 0; s < 2; ++s) {
            sr2 += ur_[s] * xrr[s] - ui_[s] * xii[s];
            si2 += ur_[s] * xii[s] + ui_[s] * xrr[s];
            kv  += c2r[s] * xrr[s] - c2i[s] * xii[s];
        }
        sr2 = wsum(sr2); si2 = wsum(si2); kv = wsum(kv);
        if (lane == 0) o_ptr[l] = kv;
        float nxr[2], nxi[2];
        #pragma unroll
        for (int s = 0; s < 2; ++s) {
            nxr[s] = er[s] * xrr[s] - ei[s] * xii[s] - (sr2 * qr[s] - si2 * qi[s]);
            nxi[s] = er[s] * xii[s] + ei[s] * xrr[s] - (sr2 * qi[s] + si2 * qr[s]);
        }
        Xr = pk(nxr[0], nxr[1]); Xi = pk(nxi[0], nxi[1]);
    }
}

extern "C" void kernel_launch(void* const* d_in, const int* in_sizes, int n_in,
                              void* d_out, int out_size) {
    const float* Ar = (const float*)d_in[0];
    const float* Ai = (const float*)d_in[1];
    const float* Br = (const float*)d_in[2];
    const float* Bi = (const float*)d_in[3];
    const float* Pr = (const float*)d_in[4];
    const float* Pi = (const float*)d_in[5];
    const float* Cr = (const float*)d_in[6];
    const float* Ci = (const float*)d_in[7];
    const float* ld = (const float*)d_in[8];
    float* out = (float*)d_out;

    const int H = in_sizes[8];          // 256
    const int L = out_size / H;         // CH = 1 -> 2048

    const int warps_per_block = 2;
    const int blocks = (H + warps_per_block - 1) / warps_per_block;
    ssm_dplr_kernel<<<blocks, warps_per_block * 32>>>(
        Ar, Ai, Br, Bi, Pr, Pi, Cr, Ci, ld, out, H, L);
}